// round 1
// baseline (speedup 1.0000x reference)
#include <cuda_runtime.h>
#include <stdint.h>
#include <math.h>

#define NELEM 32768
#define NROWS 4
#define NTHR  1024
#define CPT   32          // elements per thread
#define KSEL  1000u

// Monotone float->uint mapping (larger float => larger key)
__device__ __forceinline__ uint32_t orderKey(float f) {
    uint32_t u = __float_as_uint(f);
    return (u & 0x80000000u) ? ~u : (u | 0x80000000u);
}

__device__ __forceinline__ float blockReduceMax(float v, float* scr) {
    #pragma unroll
    for (int o = 16; o; o >>= 1) v = fmaxf(v, __shfl_xor_sync(0xFFFFFFFFu, v, o));
    if ((threadIdx.x & 31) == 0) scr[threadIdx.x >> 5] = v;
    __syncthreads();
    if (threadIdx.x < 32) {
        float x = scr[threadIdx.x];
        #pragma unroll
        for (int o = 16; o; o >>= 1) x = fmaxf(x, __shfl_xor_sync(0xFFFFFFFFu, x, o));
        if (threadIdx.x == 0) scr[0] = x;
    }
    __syncthreads();
    float r = scr[0];
    __syncthreads();
    return r;
}

__device__ __forceinline__ float blockReduceSum(float v, float* scr) {
    #pragma unroll
    for (int o = 16; o; o >>= 1) v += __shfl_xor_sync(0xFFFFFFFFu, v, o);
    if ((threadIdx.x & 31) == 0) scr[threadIdx.x >> 5] = v;
    __syncthreads();
    if (threadIdx.x < 32) {
        float x = scr[threadIdx.x];
        #pragma unroll
        for (int o = 16; o; o >>= 1) x += __shfl_xor_sync(0xFFFFFFFFu, x, o);
        if (threadIdx.x == 0) scr[0] = x;
    }
    __syncthreads();
    float r = scr[0];
    __syncthreads();
    return r;
}

__global__ __launch_bounds__(NTHR, 1)
void selection_head_kernel(const float* __restrict__ logits,
                           const float* __restrict__ gumbel,
                           float* __restrict__ out) {
    __shared__ uint32_t warpHist[32][256];       // 32 KB, per-warp private histograms
    __shared__ uint32_t hist[256];               // 1 KB
    __shared__ uint32_t selMask[NELEM / 32];     // 4 KB selection bitmask
    __shared__ uint32_t eqList[2048];            // 8 KB tie indices
    __shared__ float    fscr[32];
    __shared__ uint32_t ubx[4];                  // [0]=prefix [1]=remaining [2]=eqCount

    const int row  = blockIdx.x;
    const int t    = threadIdx.x;
    const int lane = t & 31;
    const int warp = t >> 5;
    const float* lrow = logits + row * NELEM;
    const float* grow = gumbel + row * NELEM;

    // ---- Pass 1: keys (in registers) + max(logits) ----
    uint32_t keys[CPT];
    float lmax = -INFINITY;
    #pragma unroll
    for (int i = 0; i < CPT; i++) {
        int idx = t + i * NTHR;
        float l = lrow[idx];
        float g = grow[idx];
        keys[i] = orderKey(l + g);
        lmax = fmaxf(lmax, l);
    }
    float maxL = blockReduceMax(lmax, fscr);

    // ---- Pass 2: logsumexp(logits) ----
    float lsum = 0.0f;
    #pragma unroll
    for (int i = 0; i < CPT; i++) {
        float l = lrow[t + i * NTHR];
        lsum += expf(l - maxL);
    }
    float Z = blockReduceSum(lsum, fscr);
    float logZ = maxL + logf(Z);

    // ---- Radix select: 1000th largest key, 4 rounds of 8 bits ----
    uint32_t prefix = 0, remaining = KSEL;
    #pragma unroll 1
    for (int shift = 24; shift >= 0; shift -= 8) {
        // zero per-warp histograms (8192 words / 1024 threads)
        #pragma unroll
        for (int j = 0; j < 8; j++) ((uint32_t*)warpHist)[t + j * NTHR] = 0;
        __syncthreads();

        uint32_t pm = 0;
        if (shift < 24) pm = 0xFFFFFFFFu << (shift + 8);

        #pragma unroll
        for (int i = 0; i < CPT; i++) {
            uint32_t k = keys[i];
            bool act = ((k & pm) == prefix);
            uint32_t amask = __ballot_sync(0xFFFFFFFFu, act);
            if (act) {
                uint32_t bin = (k >> shift) & 255u;
                uint32_t m = __match_any_sync(amask, bin);
                if (lane == (__ffs(m) - 1)) warpHist[warp][bin] += __popc(m);
            }
        }
        __syncthreads();

        if (t < 256) {
            uint32_t s = 0;
            #pragma unroll
            for (int w = 0; w < 32; w++) s += warpHist[w][t];
            hist[t] = s;
        }
        __syncthreads();

        if (t == 0) {
            uint32_t cum = 0;
            int b = 255;
            for (; b > 0; --b) {
                uint32_t h = hist[b];
                if (cum + h >= remaining) break;
                cum += h;
            }
            ubx[0] = prefix | ((uint32_t)b << shift);
            ubx[1] = remaining - cum;
        }
        __syncthreads();
        prefix = ubx[0];
        remaining = ubx[1];
        __syncthreads();
    }
    const uint32_t Tkey   = prefix;
    const uint32_t needEq = remaining;   // # of ==Tkey elements to take (lowest indices)

    // ---- Build selection bitmask ----
    // idx = t + i*1024 => word = warp + 32*i, bit = lane: build words with ballot.
    if (t == 0) ubx[2] = 0;
    __syncthreads();
    #pragma unroll
    for (int i = 0; i < CPT; i++) {
        int idx = t + i * NTHR;
        uint32_t k = keys[i];
        uint32_t gt = __ballot_sync(0xFFFFFFFFu, k > Tkey);
        if (lane == 0) selMask[warp + 32 * i] = gt;
        if (k == Tkey) {
            uint32_t p = atomicAdd(&ubx[2], 1u);
            if (p < 2048u) eqList[p] = (uint32_t)idx;
        }
    }
    __syncthreads();

    // tie-break: select needEq smallest indices among ==Tkey (matches lax.top_k)
    uint32_t ec = ubx[2];
    if (ec > 2048u) ec = 2048u;
    for (uint32_t e = t; e < ec; e += NTHR) {
        uint32_t idx = eqList[e];
        uint32_t rank = 0;
        for (uint32_t j = 0; j < ec; j++) rank += (eqList[j] < idx) ? 1u : 0u;
        if (rank < needEq) atomicOr(&selMask[idx >> 5], 1u << (idx & 31));
    }
    __syncthreads();

    // ---- Write outputs: values[4] | logprobs[4*N] | actions[4*N] ----
    float* outV  = out;
    float* outLP = out + NROWS;
    float* outAC = out + NROWS + NROWS * NELEM;

    #pragma unroll
    for (int i = 0; i < CPT; i++) {
        int idx = t + i * NTHR;
        uint32_t w = selMask[idx >> 5];
        bool sel = (w >> (idx & 31)) & 1u;
        float l = lrow[idx];
        outLP[row * NELEM + idx] = sel ? (l - logZ) : 0.0f;
        outAC[row * NELEM + idx] = sel ? 1.0f : 0.0f;
    }
    if (t == 0) outV[row] = 1.0f / (1.0f + expf(-maxL));
}

extern "C" void kernel_launch(void* const* d_in, const int* in_sizes, int n_in,
                              void* d_out, int out_size) {
    const float* logits = (const float*)d_in[0];
    const float* gumbel = (const float*)d_in[1];
    float* out = (float*)d_out;
    selection_head_kernel<<<NROWS, NTHR>>>(logits, gumbel, out);
}